// round 1
// baseline (speedup 1.0000x reference)
#include <cuda_runtime.h>
#include <cstdint>

// Gather 2048 columns (8 groups x 8 slices x 32 cols) from a [16384, 4096] f32
// matrix into d_out laid out as 8 concatenated [16384, 256] group blocks.
//
// One thread per float4 (4 output floats). All decompositions are powers of 2:
//   idx in [0, 16384*2048/4) = [0, 2^23)
//   g    = idx >> 20            (group: 16384*256/4 = 2^20 float4 per group)
//   row  = (idx >> 6) & 16383   (64 float4 per output row)
//   c4   = idx & 63             (float4 column within group row)
//   j    = c4 >> 3              (which 32-wide slice: 8 float4 per slice)
//   off  = c4 & 7               (float4 within slice)
//   input float4 col = g*128 + j*16 + off     (g*512 + j*64 cols, /4)
//   input row stride = 1024 float4 (4096 cols)
//
// Stores: fully contiguous STG.128. Loads: 128B-aligned 128B chunks, fully
// sectored. Pure HBM-bound copy; expect ~40us (256 MiB @ ~6.3 TB/s effective).

__global__ void __launch_bounds__(256)
slice_cat_kernel(const float4* __restrict__ in4, float4* __restrict__ out4)
{
    const uint32_t idx = blockIdx.x * 256u + threadIdx.x;   // < 2^23, exact grid
    const uint32_t g   = idx >> 20;
    const uint32_t row = (idx >> 6) & 16383u;
    const uint32_t c4  = idx & 63u;
    const uint32_t j   = c4 >> 3;
    const uint32_t off = c4 & 7u;

    const uint32_t in_idx = row * 1024u + g * 128u + j * 16u + off;
    out4[idx] = __ldg(&in4[in_idx]);
}

extern "C" void kernel_launch(void* const* d_in, const int* in_sizes, int n_in,
                              void* d_out, int out_size)
{
    (void)in_sizes; (void)n_in; (void)out_size;
    const float4* in4 = (const float4*)d_in[0];
    float4* out4 = (float4*)d_out;

    // total float4 = 16384 * 2048 / 4 = 8,388,608 = 32768 blocks * 256 threads
    slice_cat_kernel<<<32768, 256>>>(in4, out4);
}

// round 2
// speedup vs baseline: 1.0092x; 1.0092x over previous
#include <cuda_runtime.h>
#include <cstdint>

// Gather 2048 columns (8 groups x 8 slices x 32 cols) from a [16384, 4096] f32
// matrix into d_out laid out as 8 concatenated [16384, 256] group blocks.
//
// R2: unroll x4 per thread to raise per-thread MLP. Each block owns 1024
// consecutive output float4s; thread t handles idx = blk*1024 + k*256 + t for
// k=0..3. All 4 loads are issued before any store (front-batched LDG.128s ->
// deeper LSU pipeline, hides DRAM latency). Stores remain perfectly
// contiguous STG.128 per instruction across the warp.
//
// Index math (per float4 output index idx in [0, 2^23)):
//   g    = idx >> 20            (8 groups, 2^20 float4 each)
//   row  = (idx >> 6) & 16383   (64 float4 per output row)
//   c4   = idx & 63
//   j    = c4 >> 3, off = c4 & 7
//   in   = row*1024 + g*128 + j*16 + off

__global__ void __launch_bounds__(256)
slice_cat_kernel(const float4* __restrict__ in4, float4* __restrict__ out4)
{
    const uint32_t base = blockIdx.x * 1024u + threadIdx.x;

    uint32_t in_idx[4];
#pragma unroll
    for (int k = 0; k < 4; ++k) {
        const uint32_t idx = base + k * 256u;
        const uint32_t g   = idx >> 20;
        const uint32_t row = (idx >> 6) & 16383u;
        const uint32_t c4  = idx & 63u;
        in_idx[k] = row * 1024u + g * 128u + (c4 >> 3) * 16u + (c4 & 7u);
    }

    float4 v[4];
#pragma unroll
    for (int k = 0; k < 4; ++k)
        v[k] = __ldg(&in4[in_idx[k]]);

#pragma unroll
    for (int k = 0; k < 4; ++k)
        out4[base + k * 256u] = v[k];
}

extern "C" void kernel_launch(void* const* d_in, const int* in_sizes, int n_in,
                              void* d_out, int out_size)
{
    (void)in_sizes; (void)n_in; (void)out_size;
    const float4* in4 = (const float4*)d_in[0];
    float4* out4 = (float4*)d_out;

    // total float4 = 2^23; 1024 per block -> 8192 blocks
    slice_cat_kernel<<<8192, 256>>>(in4, out4);
}